// round 4
// baseline (speedup 1.0000x reference)
#include <cuda_runtime.h>
#include <cuda_bf16.h>
#include <mma.h>
#include <cstdint>

using namespace nvcuda;

#define T_DIM   2048
#define B_DIM   128
#define IN_DIM  64
#define H_DIM   128
#define G_DIM   512
#define OUT_DIM 32
#define M_TOT   (T_DIM * B_DIM)   // 262144

// scratch (device globals: allocation-free per harness rules)
__device__ float g_xp[(size_t)M_TOT * G_DIM];  // 512 MB, reused by both layers
__device__ float g_y [(size_t)M_TOT * H_DIM];  // 128 MB, layer outputs (y0 then y1)

// ---------------- activations: single-MUFU tanh.approx ----------------------
__device__ __forceinline__ float tanh_f(float x) {
    float y; asm("tanh.approx.f32 %0, %1;" : "=f"(y) : "f"(x)); return y;
}
__device__ __forceinline__ float sigmoid_f(float x) {
    return 0.5f * tanh_f(0.5f * x) + 0.5f;
}
__device__ __forceinline__ float to_tf32(float x) {
    float r; asm("cvt.rna.tf32.f32 %0, %1;" : "=f"(r) : "f"(x)); return r;
}

// ---------------- tf32x3 WMMA GEMM: C[m][g] = sum_k A[m][k]*W[g][k] ---------
// A: [M,K] row-major, W: [G_DIM,K] row-major (acts as B^T -> col_major frags).
// Block tile 128x64, whole K resident in smem. 256 threads = 8 warps (4x2),
// warp tile 32x32 (2x2 fragments of 16x16x8).
template<int K>
__global__ void __launch_bounds__(256) gemm_tc(const float* __restrict__ A,
                                               const float* __restrict__ W,
                                               float* __restrict__ C)
{
    constexpr int LDA = K + 4;                 // pad: conflict reduction, 16B-aligned rows
    extern __shared__ float smem[];
    float* As = smem;                          // [128][LDA]
    float* Ws = smem + 128 * LDA;              // [64][LDA]

    const int tid = threadIdx.x;
    const int m0 = blockIdx.y * 128, n0 = blockIdx.x * 64;

    // stage A tile (128 x K) and W tile (64 x K), float4 coalesced
    for (int i = tid; i < 128 * (K / 4); i += 256) {
        int r = i / (K / 4), cq = i % (K / 4);
        float4 v = *reinterpret_cast<const float4*>(A + (size_t)(m0 + r) * K + cq * 4);
        *reinterpret_cast<float4*>(As + r * LDA + cq * 4) = v;
    }
    for (int i = tid; i < 64 * (K / 4); i += 256) {
        int r = i / (K / 4), cq = i % (K / 4);
        float4 v = *reinterpret_cast<const float4*>(W + (size_t)(n0 + r) * K + cq * 4);
        *reinterpret_cast<float4*>(Ws + r * LDA + cq * 4) = v;
    }
    __syncthreads();

    const int warp = tid >> 5;
    const int wm = warp >> 1;                  // 0..3
    const int wn = warp & 1;                   // 0..1

    wmma::fragment<wmma::accumulator, 16, 16, 8, float> c[2][2];
    #pragma unroll
    for (int i = 0; i < 2; i++)
        #pragma unroll
        for (int j = 0; j < 2; j++) wmma::fill_fragment(c[i][j], 0.0f);

    for (int k = 0; k < K; k += 8) {
        wmma::fragment<wmma::matrix_a, 16, 16, 8, wmma::precision::tf32, wmma::row_major> ah[2], al[2];
        wmma::fragment<wmma::matrix_b, 16, 16, 8, wmma::precision::tf32, wmma::col_major> bh[2], bl[2];
        #pragma unroll
        for (int i = 0; i < 2; i++) {
            wmma::load_matrix_sync(ah[i], As + (wm * 32 + 16 * i) * LDA + k, LDA);
            #pragma unroll
            for (int e = 0; e < ah[i].num_elements; e++) {
                float v = ah[i].x[e];
                float hi = to_tf32(v);
                ah[i].x[e] = hi;
                al[i].x[e] = to_tf32(v - hi);
            }
            wmma::load_matrix_sync(bh[i], Ws + (wn * 32 + 16 * i) * LDA + k, LDA);
            #pragma unroll
            for (int e = 0; e < bh[i].num_elements; e++) {
                float v = bh[i].x[e];
                float hi = to_tf32(v);
                bh[i].x[e] = hi;
                bl[i].x[e] = to_tf32(v - hi);
            }
        }
        #pragma unroll
        for (int i = 0; i < 2; i++)
            #pragma unroll
            for (int j = 0; j < 2; j++) {
                wmma::mma_sync(c[i][j], al[i], bh[j], c[i][j]);
                wmma::mma_sync(c[i][j], ah[i], bl[j], c[i][j]);
                wmma::mma_sync(c[i][j], ah[i], bh[j], c[i][j]);
            }
    }
    #pragma unroll
    for (int i = 0; i < 2; i++)
        #pragma unroll
        for (int j = 0; j < 2; j++)
            wmma::store_matrix_sync(C + (size_t)(m0 + wm * 32 + 16 * i) * G_DIM + (n0 + wn * 32 + 16 * j),
                                    c[i][j], G_DIM, wmma::mem_row_major);
}

// ---------------- persistent per-batch LSTM recurrence ----------------------
// grid = 128 (one CTA per batch element), 512 threads (thread j = gate row).
// w_hh[j][0:64] in registers (16 float4); w_hh[j][64:128] in smem as
// float4 chunks with XOR swizzle: ws4[j*16 + (c ^ (j&7))] — conflict-free
// LDS.128 for both stores and loads (8-lane phases hit 8 distinct 16B slots).
// dyn smem: ws 64*512 f32 | h_s 128 | gate 512  = 133,632 B
#define REC_SMEM ((64 * 512 + 128 + 512) * 4)

__global__ void __launch_bounds__(512, 1) lstm_rec(const float* __restrict__ xp,
                                                   const float* __restrict__ whh,
                                                   float* __restrict__ y,
                                                   float* __restrict__ hn,
                                                   float* __restrict__ cn)
{
    extern __shared__ float sm[];
    float4* ws4  = reinterpret_cast<float4*>(sm);   // [512][16] float4, swizzled
    float*  h_s  = sm + 64 * 512;                   // [128]
    float*  gate = h_s + 128;                       // [512]

    const int b  = blockIdx.x;
    const int j  = threadIdx.x;
    const int js = j & 7;

    // load weights: row j of whh, 32 float4 chunks (k 0..127)
    const float4* wrow = reinterpret_cast<const float4*>(whh + (size_t)j * H_DIM);
    float4 wr4[16];
    #pragma unroll
    for (int c = 0; c < 16; c++) wr4[c] = wrow[c];
    #pragma unroll
    for (int c = 0; c < 16; c++) ws4[j * 16 + (c ^ js)] = wrow[16 + c];

    if (j < H_DIM) h_s[j] = 0.0f;
    float cst = 0.0f;
    __syncthreads();

    const float* xpb = xp + (size_t)b * G_DIM + j;
    float xv = xpb[0];
    const float4* h4 = reinterpret_cast<const float4*>(h_s);
    const float4* wsp = ws4 + j * 16;

    for (int t = 0; t < T_DIM; t++) {
        // prefetch next step's x-projection early (hidden under the dot)
        float xn = 0.0f;
        if (t + 1 < T_DIM) xn = xpb[(size_t)(t + 1) * B_DIM * G_DIM];

        float a0 = xv, a1 = 0.0f, a2 = 0.0f, a3 = 0.0f;
        #pragma unroll
        for (int c = 0; c < 16; c++) {
            float4 hv = h4[c];
            float4 w  = wr4[c];
            a0 = fmaf(w.x, hv.x, a0);
            a1 = fmaf(w.y, hv.y, a1);
            a2 = fmaf(w.z, hv.z, a2);
            a3 = fmaf(w.w, hv.w, a3);
        }
        #pragma unroll
        for (int c = 0; c < 16; c++) {
            float4 hv = h4[16 + c];
            float4 w  = wsp[c ^ js];
            a0 = fmaf(w.x, hv.x, a0);
            a1 = fmaf(w.y, hv.y, a1);
            a2 = fmaf(w.z, hv.z, a2);
            a3 = fmaf(w.w, hv.w, a3);
        }
        gate[j] = (a0 + a1) + (a2 + a3);
        __syncthreads();

        if (j < H_DIM) {
            float ig = sigmoid_f(gate[j]);
            float fg = sigmoid_f(gate[H_DIM + j]);
            float gg = tanh_f   (gate[2 * H_DIM + j]);
            float og = sigmoid_f(gate[3 * H_DIM + j]);
            cst = fg * cst + ig * gg;
            float h = og * tanh_f(cst);
            h_s[j] = h;
            y[((size_t)t * B_DIM + b) * H_DIM + j] = h;
        }
        __syncthreads();
        xv = xn;
    }
    if (j < H_DIM) {
        hn[b * H_DIM + j] = h_s[j];
        cn[b * H_DIM + j] = cst;
    }
}

// ---------------- FC head: out[m][o] = sum_k y[m][k]*fc_w[o][k] + b[o] ------
__global__ void __launch_bounds__(256) fc_head(const float* __restrict__ A,
                                               const float* __restrict__ W,
                                               const float* __restrict__ bias,
                                               float* __restrict__ C)
{
    __shared__ float ys[32][128];
    __shared__ float wst[128][32];
    const int tid = threadIdx.x;
    const int m0 = blockIdx.x * 32;

    for (int i = tid; i < OUT_DIM * H_DIM; i += 256) {
        int o = i / H_DIM, k = i % H_DIM;
        wst[k][o] = W[i];
    }
    for (int i = tid; i < 32 * H_DIM; i += 256) {
        int r = i / H_DIM, k = i % H_DIM;
        ys[r][k] = A[(size_t)(m0 + r) * H_DIM + k];
    }
    __syncthreads();

    const int o = tid & 31, mq = tid >> 5;
    float a0 = 0.f, a1 = 0.f, a2 = 0.f, a3 = 0.f;
    #pragma unroll 8
    for (int k = 0; k < H_DIM; k++) {
        float w = wst[k][o];
        a0 += ys[mq * 4 + 0][k] * w;
        a1 += ys[mq * 4 + 1][k] * w;
        a2 += ys[mq * 4 + 2][k] * w;
        a3 += ys[mq * 4 + 3][k] * w;
    }
    float bb = bias[o];
    C[(size_t)(m0 + mq * 4 + 0) * OUT_DIM + o] = a0 + bb;
    C[(size_t)(m0 + mq * 4 + 1) * OUT_DIM + o] = a1 + bb;
    C[(size_t)(m0 + mq * 4 + 2) * OUT_DIM + o] = a2 + bb;
    C[(size_t)(m0 + mq * 4 + 3) * OUT_DIM + o] = a3 + bb;
}

extern "C" void kernel_launch(void* const* d_in, const int* in_sizes, int n_in,
                              void* d_out, int out_size)
{
    const float* x     = (const float*)d_in[0];
    const float* w_ih0 = (const float*)d_in[1];
    const float* w_hh0 = (const float*)d_in[2];
    const float* w_ih1 = (const float*)d_in[3];
    const float* w_hh1 = (const float*)d_in[4];
    const float* fc_w  = (const float*)d_in[5];
    const float* fc_b  = (const float*)d_in[6];
    float* out = (float*)d_out;

    float* xp; cudaGetSymbolAddress((void**)&xp, g_xp);
    float* y;  cudaGetSymbolAddress((void**)&y,  g_y);

    float* hn = out + (size_t)M_TOT * OUT_DIM;            // [2,128,128]
    float* cn = hn + 2 * B_DIM * H_DIM;                   // [2,128,128]

    constexpr int SMEM64  = (128 + 64) * (64 + 4) * 4;    // 52,224 B
    constexpr int SMEM128 = (128 + 64) * (128 + 4) * 4;   // 101,376 B

    static bool attr_done = false;
    if (!attr_done) {
        cudaFuncSetAttribute(lstm_rec, cudaFuncAttributeMaxDynamicSharedMemorySize, REC_SMEM);
        cudaFuncSetAttribute(gemm_tc<IN_DIM>, cudaFuncAttributeMaxDynamicSharedMemorySize, SMEM64);
        cudaFuncSetAttribute(gemm_tc<H_DIM>,  cudaFuncAttributeMaxDynamicSharedMemorySize, SMEM128);
        attr_done = true;
    }

    dim3 gg(G_DIM / 64, M_TOT / 128);
    // layer 0
    gemm_tc<IN_DIM><<<gg, 256, SMEM64>>>(x, w_ih0, xp);
    lstm_rec<<<B_DIM, 512, REC_SMEM>>>(xp, w_hh0, y, hn, cn);
    // layer 1
    gemm_tc<H_DIM><<<gg, 256, SMEM128>>>(y, w_ih1, xp);
    lstm_rec<<<B_DIM, 512, REC_SMEM>>>(xp, w_hh1, y, hn + B_DIM * H_DIM, cn + B_DIM * H_DIM);
    // FC head
    fc_head<<<M_TOT / 32, 256>>>(y, fc_w, fc_b, out);
}

// round 5
// speedup vs baseline: 1.6022x; 1.6022x over previous
#include <cuda_runtime.h>
#include <cuda_bf16.h>
#include <mma.h>
#include <cstdint>

using namespace nvcuda;

#define T_DIM   2048
#define B_DIM   128
#define IN_DIM  64
#define H_DIM   128
#define G_DIM   512
#define OUT_DIM 32
#define M_TOT   (T_DIM * B_DIM)   // 262144

typedef unsigned long long ull;

// scratch (device globals: allocation-free per harness rules)
__device__ float g_xp[(size_t)M_TOT * G_DIM];  // 512 MB, reused by both layers
__device__ float g_y [(size_t)M_TOT * H_DIM];  // 128 MB, layer outputs (y0 then y1)

// ---------------- activations ------------------------------------------------
__device__ __forceinline__ float tanh_f(float x) {
    float y; asm("tanh.approx.f32 %0, %1;" : "=f"(y) : "f"(x)); return y;
}
__device__ __forceinline__ float sigmoid_f(float x) {
    return 0.5f * tanh_f(0.5f * x) + 0.5f;
}

// packed fp32x2 FMA (Blackwell FFMA2 — only reachable via PTX)
__device__ __forceinline__ ull fma2(ull a, ull b, ull c) {
    ull d; asm("fma.rn.f32x2 %0, %1, %2, %3;" : "=l"(d) : "l"(a), "l"(b), "l"(c));
    return d;
}
__device__ __forceinline__ float lo32(ull v) { return __uint_as_float((unsigned)(v & 0xffffffffu)); }
__device__ __forceinline__ float hi32(ull v) { return __uint_as_float((unsigned)(v >> 32)); }

// ---------------- bf16(hi+lo) tensor-core GEMM ------------------------------
// C[m][g] = sum_k A[m][k] * W[g][k].  A:[M,K] rm, W:[512,K] rm (=> B col-major).
// Split each fp32 into bf16 hi + bf16 lo ONCE at staging; 3 MMA terms:
// ah*bh + al*bh + ah*bl  (al*bl ~ 2^-18, dropped).
// Block tile 128x64, 256 threads = 8 warps (4x2), warp tile 32x32.
template<int K>
__global__ void __launch_bounds__(256) gemm_bf3(const float* __restrict__ A,
                                                const float* __restrict__ W,
                                                float* __restrict__ C)
{
    constexpr int LD = K + 8;                    // bf16 elems; row = 2*LD bytes (16B mult)
    extern __shared__ __nv_bfloat16 sb[];
    __nv_bfloat16* Ah = sb;                      // [128][LD]
    __nv_bfloat16* Al = Ah + 128 * LD;
    __nv_bfloat16* Wh = Al + 128 * LD;           // [64][LD]
    __nv_bfloat16* Wl = Wh + 64 * LD;

    const int tid = threadIdx.x;
    const int m0 = blockIdx.y * 128, n0 = blockIdx.x * 64;

    // stage + split A (128 x K) and W (64 x K); float4-coalesced reads
    for (int i = tid; i < 128 * (K / 4); i += 256) {
        int r = i / (K / 4), cq = i % (K / 4);
        float4 v = *reinterpret_cast<const float4*>(A + (size_t)(m0 + r) * K + cq * 4);
        float vv[4] = {v.x, v.y, v.z, v.w};
        #pragma unroll
        for (int e = 0; e < 4; e++) {
            __nv_bfloat16 h = __float2bfloat16_rn(vv[e]);
            Ah[r * LD + cq * 4 + e] = h;
            Al[r * LD + cq * 4 + e] = __float2bfloat16_rn(vv[e] - __bfloat162float(h));
        }
    }
    for (int i = tid; i < 64 * (K / 4); i += 256) {
        int r = i / (K / 4), cq = i % (K / 4);
        float4 v = *reinterpret_cast<const float4*>(W + (size_t)(n0 + r) * K + cq * 4);
        float vv[4] = {v.x, v.y, v.z, v.w};
        #pragma unroll
        for (int e = 0; e < 4; e++) {
            __nv_bfloat16 h = __float2bfloat16_rn(vv[e]);
            Wh[r * LD + cq * 4 + e] = h;
            Wl[r * LD + cq * 4 + e] = __float2bfloat16_rn(vv[e] - __bfloat162float(h));
        }
    }
    __syncthreads();

    const int warp = tid >> 5;
    const int wm = warp >> 1, wn = warp & 1;

    wmma::fragment<wmma::accumulator, 16, 16, 16, float> c[2][2];
    #pragma unroll
    for (int i = 0; i < 2; i++)
        #pragma unroll
        for (int j = 0; j < 2; j++) wmma::fill_fragment(c[i][j], 0.0f);

    for (int k = 0; k < K; k += 16) {
        wmma::fragment<wmma::matrix_a, 16, 16, 16, __nv_bfloat16, wmma::row_major> ah[2], al[2];
        wmma::fragment<wmma::matrix_b, 16, 16, 16, __nv_bfloat16, wmma::col_major> bh[2], bl[2];
        #pragma unroll
        for (int i = 0; i < 2; i++) {
            wmma::load_matrix_sync(ah[i], Ah + (wm * 32 + 16 * i) * LD + k, LD);
            wmma::load_matrix_sync(al[i], Al + (wm * 32 + 16 * i) * LD + k, LD);
            wmma::load_matrix_sync(bh[i], Wh + (wn * 32 + 16 * i) * LD + k, LD);
            wmma::load_matrix_sync(bl[i], Wl + (wn * 32 + 16 * i) * LD + k, LD);
        }
        #pragma unroll
        for (int i = 0; i < 2; i++)
            #pragma unroll
            for (int j = 0; j < 2; j++) {
                wmma::mma_sync(c[i][j], al[i], bh[j], c[i][j]);
                wmma::mma_sync(c[i][j], ah[i], bl[j], c[i][j]);
                wmma::mma_sync(c[i][j], ah[i], bh[j], c[i][j]);
            }
    }
    #pragma unroll
    for (int i = 0; i < 2; i++)
        #pragma unroll
        for (int j = 0; j < 2; j++)
            wmma::store_matrix_sync(C + (size_t)(m0 + wm * 32 + 16 * i) * G_DIM + (n0 + wn * 32 + 16 * j),
                                    c[i][j], G_DIM, wmma::mem_row_major);
}

// ---------------- persistent per-batch LSTM recurrence ----------------------
// grid = 128 (one CTA per batch element), 256 threads.
// Thread j handles gate rows j and j+256.  (j<128: i & g gates; j>=128: f & o.)
// Weights: k in [0,96) in 48 b64 registers per row (f32x2 packed);
//          k in [96,128) in smem ws2[chunk][row] (ulonglong2, conflict-free).
// Math: packed fma.rn.f32x2, h read as broadcast ulonglong2 chunks.
// dyn smem: ws2 8*512*16 = 65536 B | h_s 128 f | fsig 128 f | osig 128 f
#define REC_SMEM (65536 + 128 * 4 * 3)

__global__ void __launch_bounds__(256, 1) lstm_rec(const float* __restrict__ xp,
                                                   const float* __restrict__ whh,
                                                   float* __restrict__ y,
                                                   float* __restrict__ hn,
                                                   float* __restrict__ cn)
{
    extern __shared__ __align__(16) char smraw[];
    ulonglong2* ws2  = reinterpret_cast<ulonglong2*>(smraw);      // [8][512]
    float*      h_s  = reinterpret_cast<float*>(smraw + 65536);   // [128]
    float*      fsig = h_s + 128;                                  // [128]
    float*      osig = fsig + 128;                                 // [128]

    const int b  = blockIdx.x;
    const int j  = threadIdx.x;           // 0..255
    const int rA = j;                     // gate row A
    const int rB = j + 256;               // gate row B

    // ---- load weights ----
    const ull* wrowA = reinterpret_cast<const ull*>(whh + (size_t)rA * H_DIM);
    const ull* wrowB = reinterpret_cast<const ull*>(whh + (size_t)rB * H_DIM);
    ull wa[48], wb[48];
    #pragma unroll
    for (int u = 0; u < 48; u++) { wa[u] = wrowA[u]; wb[u] = wrowB[u]; }
    const ulonglong2* wrA2 = reinterpret_cast<const ulonglong2*>(wrowA);
    const ulonglong2* wrB2 = reinterpret_cast<const ulonglong2*>(wrowB);
    #pragma unroll
    for (int c = 0; c < 8; c++) {
        ws2[c * 512 + rA] = wrA2[24 + c];
        ws2[c * 512 + rB] = wrB2[24 + c];
    }
    if (j < H_DIM) h_s[j] = 0.0f;
    float cst = 0.0f;
    __syncthreads();

    const float* xpA = xp + (size_t)b * G_DIM + rA;
    const float* xpB = xp + (size_t)b * G_DIM + rB;
    float xvA = xpA[0], xvB = xpB[0];
    const ulonglong2* h22 = reinterpret_cast<const ulonglong2*>(h_s);

    for (int t = 0; t < T_DIM; t++) {
        // prefetch next step's x-projection (hidden under the dot product)
        float xnA = 0.0f, xnB = 0.0f;
        if (t + 1 < T_DIM) {
            size_t off = (size_t)(t + 1) * B_DIM * G_DIM;
            xnA = xpA[off]; xnB = xpB[off];
        }

        ull aA0 = 0, aA1 = 0, aB0 = 0, aB1 = 0;
        #pragma unroll
        for (int c = 0; c < 24; c++) {               // k 0..95: weights in regs
            ulonglong2 hv = h22[c];                  // LDS.128 broadcast
            aA0 = fma2(wa[2 * c],     hv.x, aA0);
            aA1 = fma2(wa[2 * c + 1], hv.y, aA1);
            aB0 = fma2(wb[2 * c],     hv.x, aB0);
            aB1 = fma2(wb[2 * c + 1], hv.y, aB1);
        }
        #pragma unroll
        for (int c = 0; c < 8; c++) {                // k 96..127: weights in smem
            ulonglong2 hv = h22[24 + c];
            ulonglong2 wvA = ws2[c * 512 + rA];
            ulonglong2 wvB = ws2[c * 512 + rB];
            aA0 = fma2(wvA.x, hv.x, aA0);
            aA1 = fma2(wvA.y, hv.y, aA1);
            aB0 = fma2(wvB.x, hv.x, aB0);
            aB1 = fma2(wvB.y, hv.y, aB1);
        }
        float gA = xvA + ((lo32(aA0) + hi32(aA0)) + (lo32(aA1) + hi32(aA1)));
        float gB = xvB + ((lo32(aB0) + hi32(aB0)) + (lo32(aB1) + hi32(aB1)));

        float iact = 0.0f, gact = 0.0f;
        if (j < 128) {                   // rows j (i-gate) and j+256 (g-gate)
            iact = sigmoid_f(gA);
            gact = tanh_f(gB);
        } else {                         // rows 128+m (f) and 384+m (o)
            fsig[j - 128] = sigmoid_f(gA);
            osig[j - 128] = sigmoid_f(gB);
        }
        __syncthreads();
        if (j < 128) {
            cst = fsig[j] * cst + iact * gact;
            float h = osig[j] * tanh_f(cst);
            h_s[j] = h;
            y[((size_t)t * B_DIM + b) * H_DIM + j] = h;
        }
        __syncthreads();
        xvA = xnA; xvB = xnB;
    }
    if (j < 128) {
        hn[b * H_DIM + j] = h_s[j];
        cn[b * H_DIM + j] = cst;
    }
}

// ---------------- FC head: out[m][o] = sum_k y[m][k]*fc_w[o][k] + b[o] ------
__global__ void __launch_bounds__(256) fc_head(const float* __restrict__ A,
                                               const float* __restrict__ W,
                                               const float* __restrict__ bias,
                                               float* __restrict__ C)
{
    __shared__ float ys[32][128];
    __shared__ float wst[128][32];
    const int tid = threadIdx.x;
    const int m0 = blockIdx.x * 32;

    for (int i = tid; i < OUT_DIM * H_DIM; i += 256) {
        int o = i / H_DIM, k = i % H_DIM;
        wst[k][o] = W[i];
    }
    for (int i = tid; i < 32 * H_DIM; i += 256) {
        int r = i / H_DIM, k = i % H_DIM;
        ys[r][k] = A[(size_t)(m0 + r) * H_DIM + k];
    }
    __syncthreads();

    const int o = tid & 31, mq = tid >> 5;
    float a0 = 0.f, a1 = 0.f, a2 = 0.f, a3 = 0.f;
    #pragma unroll 8
    for (int k = 0; k < H_DIM; k++) {
        float w = wst[k][o];
        a0 += ys[mq * 4 + 0][k] * w;
        a1 += ys[mq * 4 + 1][k] * w;
        a2 += ys[mq * 4 + 2][k] * w;
        a3 += ys[mq * 4 + 3][k] * w;
    }
    float bb = bias[o];
    C[(size_t)(m0 + mq * 4 + 0) * OUT_DIM + o] = a0 + bb;
    C[(size_t)(m0 + mq * 4 + 1) * OUT_DIM + o] = a1 + bb;
    C[(size_t)(m0 + mq * 4 + 2) * OUT_DIM + o] = a2 + bb;
    C[(size_t)(m0 + mq * 4 + 3) * OUT_DIM + o] = a3 + bb;
}

extern "C" void kernel_launch(void* const* d_in, const int* in_sizes, int n_in,
                              void* d_out, int out_size)
{
    const float* x     = (const float*)d_in[0];
    const float* w_ih0 = (const float*)d_in[1];
    const float* w_hh0 = (const float*)d_in[2];
    const float* w_ih1 = (const float*)d_in[3];
    const float* w_hh1 = (const float*)d_in[4];
    const float* fc_w  = (const float*)d_in[5];
    const float* fc_b  = (const float*)d_in[6];
    float* out = (float*)d_out;

    float* xp; cudaGetSymbolAddress((void**)&xp, g_xp);
    float* y;  cudaGetSymbolAddress((void**)&y,  g_y);

    float* hn = out + (size_t)M_TOT * OUT_DIM;            // [2,128,128]
    float* cn = hn + 2 * B_DIM * H_DIM;                   // [2,128,128]

    constexpr int SMEM64  = (128 + 64) * (64 + 8) * 2 * 2;    // 55,296 B
    constexpr int SMEM128 = (128 + 64) * (128 + 8) * 2 * 2;   // 104,448 B

    static bool attr_done = false;
    if (!attr_done) {
        cudaFuncSetAttribute(lstm_rec, cudaFuncAttributeMaxDynamicSharedMemorySize, REC_SMEM);
        cudaFuncSetAttribute(gemm_bf3<IN_DIM>, cudaFuncAttributeMaxDynamicSharedMemorySize, SMEM64);
        cudaFuncSetAttribute(gemm_bf3<H_DIM>,  cudaFuncAttributeMaxDynamicSharedMemorySize, SMEM128);
        attr_done = true;
    }

    dim3 gg(G_DIM / 64, M_TOT / 128);
    // layer 0
    gemm_bf3<IN_DIM><<<gg, 256, SMEM64>>>(x, w_ih0, xp);
    lstm_rec<<<B_DIM, 256, REC_SMEM>>>(xp, w_hh0, y, hn, cn);
    // layer 1
    gemm_bf3<H_DIM><<<gg, 256, SMEM128>>>(y, w_ih1, xp);
    lstm_rec<<<B_DIM, 256, REC_SMEM>>>(xp, w_hh1, y, hn + B_DIM * H_DIM, cn + B_DIM * H_DIM);
    // FC head
    fc_head<<<M_TOT / 32, 256>>>(y, fc_w, fc_b, out);
}